// round 14
// baseline (speedup 1.0000x reference)
#include <cuda_runtime.h>
#include <cuda_fp16.h>
#include <math.h>
#include <stdint.h>

typedef unsigned short u16;

#define E_EXP   16
#define TOPK    2
#define D_IN    256
#define D_H     512
#define D_OUT   256
#define BATCH   32768
#define NSLOT   (BATCH * TOPK)
#define TM      128

#define RSTRIDE 80               // padded smem row stride (bytes), 32 fp16 per row
#define PLANE   (128 * RSTRIDE)  // 10240 B

// ---------------- scratch (__device__ globals) ------------------------------
__device__ int   g_counts[E_EXP];
__device__ int   g_offsets[E_EXP + 1];
__device__ int   g_cursor[E_EXP];
__device__ int   g_topk_e[NSLOT];
__device__ float g_topk_w[NSLOT];
__device__ int   g_perm[NSLOT];
__device__ u16   g_xh [(size_t)BATCH * D_IN];        // x fp16
__device__ u16   g_w1h[(size_t)E_EXP * D_H * D_IN];  // W1^T [e][n][k] fp16
__device__ u16   g_w2h[(size_t)E_EXP * D_OUT * D_H]; // W2^T [e][o][h] fp16
__device__ u16   g_hh [(size_t)NSLOT * D_H];         // H fp16
__device__ float g_y  [(size_t)NSLOT * D_OUT];       // per-slot outputs

// ---------------- helpers ---------------------------------------------------
__device__ __forceinline__ uint32_t smem_u32(const void* p) {
    uint32_t a;
    asm("{ .reg .u64 t; cvta.to.shared.u64 t, %1; cvt.u32.u64 %0, t; }" : "=r"(a) : "l"(p));
    return a;
}
__device__ __forceinline__ void cpa16(uint32_t dst, const void* src) {
    asm volatile("cp.async.cg.shared.global [%0], [%1], 16;" :: "r"(dst), "l"(src));
}
#define CP_COMMIT() asm volatile("cp.async.commit_group;" ::: "memory")
#define CP_WAIT1()  asm volatile("cp.async.wait_group 1;" ::: "memory")
#define CP_WAIT2()  asm volatile("cp.async.wait_group 2;" ::: "memory")

__device__ __forceinline__ void mma_f16(float c[4], const uint32_t a[4], const uint32_t b[2]) {
    asm volatile(
        "mma.sync.aligned.m16n8k16.row.col.f32.f16.f16.f32 "
        "{%0,%1,%2,%3}, {%4,%5,%6,%7}, {%8,%9}, {%0,%1,%2,%3};"
        : "+f"(c[0]), "+f"(c[1]), "+f"(c[2]), "+f"(c[3])
        : "r"(a[0]), "r"(a[1]), "r"(a[2]), "r"(a[3]), "r"(b[0]), "r"(b[1]));
}
__device__ __forceinline__ void ldsm_x4(uint32_t r[4], uint32_t addr) {
    asm volatile("ldmatrix.sync.aligned.m8n8.x4.shared.b16 {%0,%1,%2,%3}, [%4];"
        : "=r"(r[0]), "=r"(r[1]), "=r"(r[2]), "=r"(r[3]) : "r"(addr));
}
__device__ __forceinline__ u16 to_h(float v) {
    return __half_as_ushort(__float2half(v));
}

// ---------------- reset / gating(+pack x) / scan / scatter -------------------
__global__ void reset_kernel() {
    int i = threadIdx.x;
    if (i < E_EXP) g_counts[i] = 0;
}

__global__ void gating_kernel(const float* __restrict__ x,
                              const float* __restrict__ Wg,
                              const float* __restrict__ bg) {
    int warp = (blockIdx.x * blockDim.x + threadIdx.x) >> 5;
    int lane = threadIdx.x & 31;
    if (warp >= BATCH) return;
    const float* xr = x + (size_t)warp * D_IN;

    float acc[E_EXP];
#pragma unroll
    for (int e = 0; e < E_EXP; e++) acc[e] = 0.f;
#pragma unroll
    for (int i = 0; i < D_IN / 32; i++) {
        float xv = xr[i * 32 + lane];
        g_xh[(size_t)warp * D_IN + i * 32 + lane] = to_h(xv);   // fused fp16 pack
        const float* wr = Wg + (size_t)(i * 32 + lane) * E_EXP;
#pragma unroll
        for (int e = 0; e < E_EXP; e++) acc[e] = fmaf(xv, wr[e], acc[e]);
    }
#pragma unroll
    for (int e = 0; e < E_EXP; e++) {
        float v = acc[e];
        v += __shfl_xor_sync(0xffffffffu, v, 16);
        v += __shfl_xor_sync(0xffffffffu, v, 8);
        v += __shfl_xor_sync(0xffffffffu, v, 4);
        v += __shfl_xor_sync(0xffffffffu, v, 2);
        v += __shfl_xor_sync(0xffffffffu, v, 1);
        acc[e] = v + bg[e];
    }
    if (lane == 0) {
        int i0 = 0; float v0 = acc[0];
#pragma unroll
        for (int e = 1; e < E_EXP; e++)
            if (acc[e] > v0) { v0 = acc[e]; i0 = e; }
        int i1 = -1; float v1 = -3.4e38f;
#pragma unroll
        for (int e = 0; e < E_EXP; e++)
            if (e != i0 && acc[e] > v1) { v1 = acc[e]; i1 = e; }
        float w0 = 1.f / (1.f + expf(v1 - v0));
        g_topk_e[warp * 2 + 0] = i0;
        g_topk_e[warp * 2 + 1] = i1;
        g_topk_w[warp * 2 + 0] = w0;
        g_topk_w[warp * 2 + 1] = 1.f - w0;
        atomicAdd(&g_counts[i0], 1);
        atomicAdd(&g_counts[i1], 1);
    }
}

__global__ void scan_kernel() {
    if (threadIdx.x == 0) {
        int s = 0;
        for (int e = 0; e < E_EXP; e++) {
            g_offsets[e] = s;
            g_cursor[e]  = s;
            s += g_counts[e];
        }
        g_offsets[E_EXP] = s;
    }
}

__global__ void scatter_kernel() {
    __shared__ int hist[E_EXP];
    __shared__ int base[E_EXP];
    int tid = threadIdx.x;
    if (tid < E_EXP) hist[tid] = 0;
    __syncthreads();
    int i = blockIdx.x * 256 + tid;
    int e = g_topk_e[i];
    int rank = atomicAdd(&hist[e], 1);
    __syncthreads();
    if (tid < E_EXP) base[tid] = atomicAdd(&g_cursor[tid], hist[tid]);
    __syncthreads();
    g_perm[base[e] + rank] = i;
}

// ---------------- prep: weight transpose + fp16 ------------------------------
__global__ void pack_transpose_kernel(const float* __restrict__ in,
                                      int which, int Kd, int Nd) {
    u16* oh = which ? g_w2h : g_w1h;
    __shared__ float t[32][33];
    int e  = blockIdx.z;
    int k0 = blockIdx.x * 32, n0 = blockIdx.y * 32;
    const float* ine = in + (size_t)e * Kd * Nd;
    u16* ohe = oh + (size_t)e * Kd * Nd;
    int tx = threadIdx.x, ty = threadIdx.y;
#pragma unroll
    for (int i = 0; i < 4; i++) {
        int k = k0 + ty + i * 8;
        t[ty + i * 8][tx] = ine[(size_t)k * Nd + n0 + tx];
    }
    __syncthreads();
#pragma unroll
    for (int i = 0; i < 4; i++) {
        int n = n0 + ty + i * 8;
        ohe[(size_t)n * Kd + k0 + tx] = to_h(t[tx][ty + i * 8]);
    }
}

// ---------------- GEMM1: H = relu(X @ W1 + b1), A-resident, 3 B-buffers ------
// smem: A resident 8 slabs (81920) | B 3-stage (30720) | bias | srow | sent
#define G1_A    0
#define G1_B    81920
#define G1_BIAS 112640               // 512 floats
#define G1_SROW (G1_BIAS + 2048)     // 114688
#define G1_SENT (G1_SROW + 512)      // 115200
#define G1_SIZE (G1_SENT + 512)      // 115712  (fits 2 CTAs if limit allows;
                                     //  fallback handled below by B size calc)
// NOTE: A resident is 8*PLANE = 81920; keep total under occ-2 limit:
// 81920 + 3*10240 + 2048 + 1024 = 115712 <= 116224 (227.5KB/2). OK.

__global__ void __launch_bounds__(256, 2)
gemm1_kernel(const float* __restrict__ b1) {
    int e = blockIdx.y, tile = blockIdx.x;
    int beg = g_offsets[e];
    int cnt = g_offsets[e + 1] - beg;
    int m0  = tile * TM;
    if (m0 >= cnt) return;

    extern __shared__ char sm[];
    uint32_t smb = smem_u32(sm);
    int tid  = threadIdx.x;
    int wid  = tid >> 5, lane = tid & 31;
    int warpM = wid >> 1, warpN = wid & 1;      // 4 (M) x 2 (N)
    int lr = lane >> 2, lc2 = (lane & 3) * 2;

    int*   srow = (int*)(sm + G1_SROW);
    int*   sent = (int*)(sm + G1_SENT);
    float* bias = (float*)(sm + G1_BIAS);

    if (tid < TM) {
        int g = beg + m0 + tid;
        if (m0 + tid < cnt) {
            int entry = g_perm[g];
            srow[tid] = entry >> 1;
            sent[tid] = entry;
        } else {
            srow[tid] = 0;
            sent[tid] = -1;
        }
    }
    bias[tid]       = b1[e * D_H + tid];
    bias[tid + 256] = b1[e * D_H + tid + 256];
    __syncthreads();

    const char* Xh = (const char*)g_xh;
    const char* Wh = (const char*)g_w1h + (size_t)e * D_H * D_IN * 2;

    int row  = tid >> 1, half = tid & 1;
    int xrow = srow[row];

    // ---- prologue: A resident (8 slabs, one commit group) ----
    {
        size_t sa = ((size_t)xrow * D_IN + half * 16) * 2;
        uint32_t da = smb + G1_A + row * RSTRIDE + half * 32;
#pragma unroll
        for (int kc = 0; kc < 8; kc++) {
            cpa16(da + kc * PLANE,      Xh + sa + kc * 64);
            cpa16(da + kc * PLANE + 16, Xh + sa + kc * 64 + 16);
        }
        CP_COMMIT();
    }

#define G1_BISSUE(ITER, BUF)                                                       \
    do {                                                                           \
        int nc_ = (ITER) >> 3, kc_ = (ITER) & 7;                                   \
        uint32_t d = smb + G1_B + (BUF) * PLANE + row * RSTRIDE + half * 32;       \
        size_t sb = ((size_t)(nc_ * 128 + row) * D_IN + kc_ * 32 + half * 16) * 2; \
        cpa16(d,      Wh + sb);                                                    \
        cpa16(d + 16, Wh + sb + 16);                                               \
        CP_COMMIT();                                                               \
    } while (0)

    G1_BISSUE(0, 0);
    G1_BISSUE(1, 1);

    uint32_t aoff = (uint32_t)(warpM * 32 + (lane & 15)) * RSTRIDE + ((lane >> 4) << 4);
    uint32_t boff = (uint32_t)(warpN * 64 + (lane & 7) + (((lane >> 4) & 1) << 3)) * RSTRIDE
                  + (((lane >> 3) & 1) << 4);

    float c[2][8][4];
    int buf = 0;

    for (int it = 0; it < 32; it++) {
        int nc = it >> 3, kc = it & 7;
        CP_WAIT1();
        __syncthreads();
        if (it + 2 < 32) {                        // 3 buffers: safe to issue now
            int nb = buf + 2; if (nb >= 3) nb -= 3;
            G1_BISSUE(it + 2, nb);
        }
        if (kc == 0) {
#pragma unroll
            for (int mi = 0; mi < 2; mi++)
#pragma unroll
                for (int ni = 0; ni < 8; ni++)
#pragma unroll
                    for (int q = 0; q < 4; q++) c[mi][ni][q] = 0.f;
        }
        uint32_t aBase = smb + G1_A + kc * PLANE + aoff;
        uint32_t bBase = smb + G1_B + buf * PLANE + boff;
#pragma unroll
        for (int k16 = 0; k16 < 2; k16++) {
            uint32_t ah[2][4], bh[8][2];
#pragma unroll
            for (int mi = 0; mi < 2; mi++)
                ldsm_x4(ah[mi], aBase + mi * (16 * RSTRIDE) + k16 * 32);
#pragma unroll
            for (int p = 0; p < 4; p++) {
                uint32_t r4[4];
                ldsm_x4(r4, bBase + p * (16 * RSTRIDE) + k16 * 32);
                bh[2 * p][0] = r4[0]; bh[2 * p][1] = r4[1];
                bh[2 * p + 1][0] = r4[2]; bh[2 * p + 1][1] = r4[3];
            }
#pragma unroll
            for (int mi = 0; mi < 2; mi++)
#pragma unroll
                for (int ni = 0; ni < 8; ni++) mma_f16(c[mi][ni], ah[mi], bh[ni]);
        }
        if (kc == 7) {
#pragma unroll
            for (int mi = 0; mi < 2; mi++) {
                int r0 = warpM * 32 + mi * 16 + lr;
#pragma unroll
                for (int ni = 0; ni < 8; ni++) {
                    int n = nc * 128 + warpN * 64 + ni * 8 + lc2;
                    float b0 = bias[n], b1v = bias[n + 1];
#pragma unroll
                    for (int hh = 0; hh < 2; hh++) {
                        int rr = r0 + hh * 8;
                        if (sent[rr] >= 0) {
                            float v0 = c[mi][ni][hh * 2 + 0] + b0;
                            float v1 = c[mi][ni][hh * 2 + 1] + b1v;
                            v0 = v0 > 0.f ? v0 : 0.f;
                            v1 = v1 > 0.f ? v1 : 0.f;
                            size_t o = (size_t)(beg + m0 + rr) * D_H + n;
                            *(uint32_t*)&g_hh[o] =
                                (uint32_t)to_h(v0) | ((uint32_t)to_h(v1) << 16);
                        }
                    }
                }
            }
        }
        if (++buf == 3) buf = 0;
    }
#undef G1_BISSUE
}

// ---------------- GEMM2: y = w * (H @ W2 + b2), 4-stage stream, 32x64 --------
#define STAGE2  (2 * PLANE)          // A|B per stage = 20480
#define G2_BIAS (4 * STAGE2)         // 81920: 256 floats
#define G2_SENT (G2_BIAS + 1024)     // 82944
#define G2_SW   (G2_SENT + 512)      // 83456
#define G2_SIZE (G2_SW + 512)        // 83968

__global__ void __launch_bounds__(256, 2)
gemm2_kernel(const float* __restrict__ b2) {
    int e = blockIdx.y, tile = blockIdx.x;
    int beg = g_offsets[e];
    int cnt = g_offsets[e + 1] - beg;
    int m0  = tile * TM;
    if (m0 >= cnt) return;

    extern __shared__ char sm[];
    uint32_t smb = smem_u32(sm);
    int tid  = threadIdx.x;
    int wid  = tid >> 5, lane = tid & 31;
    int warpM = wid >> 1, warpN = wid & 1;
    int lr = lane >> 2, lc2 = (lane & 3) * 2;

    int*   sent = (int*)(sm + G2_SENT);
    float* swv  = (float*)(sm + G2_SW);
    float* bias = (float*)(sm + G2_BIAS);

    if (tid < TM) {
        int g = beg + m0 + tid;
        if (m0 + tid < cnt) {
            int entry = g_perm[g];
            sent[tid] = entry;
            swv[tid]  = g_topk_w[entry];
        } else {
            sent[tid] = -1;
            swv[tid]  = 0.f;
        }
    }
    if (tid < 256) bias[tid] = b2[e * D_OUT + tid];
    __syncthreads();

    const char* Hh  = (const char*)g_hh;
    const char* W2h = (const char*)g_w2h + (size_t)e * D_OUT * D_H * 2;

    int row  = tid >> 1, half = tid & 1;
    int arow = (m0 + row < cnt) ? (beg + m0 + row) : beg;

#define G2_ISSUE(ITER, BUF)                                                        \
    do {                                                                           \
        int nc_ = (ITER) >> 4, kc_ = (ITER) & 15;                                  \
        uint32_t d = smb + (BUF) * STAGE2 + row * RSTRIDE + half * 32;             \
        size_t sa = ((size_t)arow * D_H + kc_ * 32 + half * 16) * 2;               \
        size_t sb = ((size_t)(nc_ * 128 + row) * D_H + kc_ * 32 + half * 16) * 2;  \
        cpa16(d,              Hh + sa);                                            \
        cpa16(d + 16,         Hh + sa + 16);                                       \
        cpa16(d + PLANE,      W2h + sb);                                           \
        cpa16(d + PLANE + 16, W2h + sb + 16);                                      \
        CP_COMMIT();                                                               \
    } while (0)

    G2_ISSUE(0, 0);
    G2_ISSUE(1, 1);
    G2_ISSUE(2, 2);

    uint32_t aoff = (uint32_t)(warpM * 32 + (lane & 15)) * RSTRIDE + ((lane >> 4) << 4);
    uint32_t boff = (uint32_t)(warpN * 64 + (lane & 7) + (((lane >> 4) & 1) << 3)) * RSTRIDE
                  + (((lane >> 3) & 1) << 4);

    float c[2][8][4];
    int buf = 0;

    for (int it = 0; it < 32; it++) {
        int nc = it >> 4, kc = it & 15;
        CP_WAIT2();
        __syncthreads();
        if (it + 3 < 32) {
            int nb = buf + 3; if (nb >= 4) nb -= 4;
            G2_ISSUE(it + 3, nb);
        }
        if (kc == 0) {
#pragma unroll
            for (int mi = 0; mi < 2; mi++)
#pragma unroll
                for (int ni = 0; ni < 8; ni++)
#pragma unroll
                    for (int q = 0; q < 4; q++) c[mi][ni][q] = 0.f;
        }
        uint32_t base  = smb + buf * STAGE2;
        uint32_t aBase = base + aoff;
        uint32_t bBase = base + PLANE + boff;
#pragma unroll
        for (int k16 = 0; k16 < 2; k16++) {
            uint32_t ah[2][4], bh[8][2];
#pragma unroll
            for (int mi = 0; mi < 2; mi++)
                ldsm_x4(ah[mi], aBase + mi * (16 * RSTRIDE) + k16 * 32);
#pragma unroll
            for (int p = 0; p < 4; p++) {
                uint32_t r4[4];
                ldsm_x4(r4, bBase + p * (16 * RSTRIDE) + k16 * 32);
                bh[2 * p][0] = r4[0]; bh[2 * p][1] = r4[1];
                bh[2 * p + 1][0] = r4[2]; bh[2 * p + 1][1] = r4[3];
            }
#pragma unroll
            for (int mi = 0; mi < 2; mi++)
#pragma unroll
                for (int ni = 0; ni < 8; ni++) mma_f16(c[mi][ni], ah[mi], bh[ni]);
        }
        if (kc == 15) {
#pragma unroll
            for (int mi = 0; mi < 2; mi++) {
                int r0 = warpM * 32 + mi * 16 + lr;
#pragma unroll
                for (int ni = 0; ni < 8; ni++) {
                    int n = nc * 128 + warpN * 64 + ni * 8 + lc2;
                    float b0 = bias[n], b1v = bias[n + 1];
#pragma unroll
                    for (int hh = 0; hh < 2; hh++) {
                        int rr = r0 + hh * 8;
                        int entry = sent[rr];
                        if (entry >= 0) {
                            float w = swv[rr];
                            float2 o;
                            o.x = w * (c[mi][ni][hh * 2 + 0] + b0);
                            o.y = w * (c[mi][ni][hh * 2 + 1] + b1v);
                            *(float2*)&g_y[(size_t)entry * D_OUT + n] = o;
                        }
                    }
                }
            }
        }
        if (++buf == 4) buf = 0;
    }
#undef G2_ISSUE
}

// ---------------- combine ---------------------------------------------------
__global__ void combine_kernel(float* __restrict__ out) {
    int i = blockIdx.x * blockDim.x + threadIdx.x;
    int b = i >> 6, q = i & 63;
    const float4* y4 = (const float4*)g_y;
    float4 u = y4[(size_t)(b * 2 + 0) * (D_OUT / 4) + q];
    float4 v = y4[(size_t)(b * 2 + 1) * (D_OUT / 4) + q];
    float4 o;
    o.x = u.x + v.x; o.y = u.y + v.y; o.z = u.z + v.z; o.w = u.w + v.w;
    ((float4*)out)[i] = o;
}

// ---------------- launch -----------------------------------------------------
extern "C" void kernel_launch(void* const* d_in, const int* in_sizes, int n_in,
                              void* d_out, int out_size) {
    const float* x  = (const float*)d_in[0];
    const float* Wg = (const float*)d_in[1];
    const float* bg = (const float*)d_in[2];
    const float* W1 = (const float*)d_in[3];
    const float* b1 = (const float*)d_in[4];
    const float* W2 = (const float*)d_in[5];
    const float* b2 = (const float*)d_in[6];
    float* out = (float*)d_out;

    cudaFuncSetAttribute(gemm1_kernel, cudaFuncAttributeMaxDynamicSharedMemorySize, G1_SIZE);
    cudaFuncSetAttribute(gemm2_kernel, cudaFuncAttributeMaxDynamicSharedMemorySize, G2_SIZE);

    reset_kernel<<<1, 32>>>();
    gating_kernel<<<BATCH / 8, 256>>>(x, Wg, bg);
    scan_kernel<<<1, 32>>>();
    scatter_kernel<<<NSLOT / 256, 256>>>();
    pack_transpose_kernel<<<dim3(D_IN / 32, D_H / 32, E_EXP), dim3(32, 8)>>>(W1, 0, D_IN, D_H);
    pack_transpose_kernel<<<dim3(D_H / 32, D_OUT / 32, E_EXP), dim3(32, 8)>>>(W2, 1, D_H, D_OUT);
    gemm1_kernel<<<dim3(NSLOT / TM, E_EXP), 256, G1_SIZE>>>(b1);
    gemm2_kernel<<<dim3(NSLOT / TM, E_EXP), 256, G2_SIZE>>>(b2);
    combine_kernel<<<(BATCH * (D_OUT / 4)) / 256, 256>>>(out);
}

// round 15
// speedup vs baseline: 1.0076x; 1.0076x over previous
#include <cuda_runtime.h>
#include <cuda_fp16.h>
#include <math.h>
#include <stdint.h>

typedef unsigned short u16;

#define E_EXP   16
#define TOPK    2
#define D_IN    256
#define D_H     512
#define D_OUT   256
#define BATCH   32768
#define NSLOT   (BATCH * TOPK)
#define TM      128

#define RSTRIDE 80               // padded smem row stride (bytes), 32 fp16 per row
#define PLANE   (128 * RSTRIDE)  // 10240 B

// ---------------- scratch (__device__ globals) ------------------------------
__device__ int   g_counts[E_EXP];
__device__ int   g_offsets[E_EXP + 1];
__device__ int   g_cursor[E_EXP];
__device__ int   g_topk_e[NSLOT];
__device__ float g_topk_w[NSLOT];
__device__ int   g_perm[NSLOT];
__device__ u16   g_xh [(size_t)BATCH * D_IN];        // x fp16
__device__ u16   g_w1h[(size_t)E_EXP * D_H * D_IN];  // W1^T [e][n][k] fp16
__device__ u16   g_w2h[(size_t)E_EXP * D_OUT * D_H]; // W2^T [e][o][h] fp16
__device__ u16   g_hh [(size_t)NSLOT * D_H];         // H fp16
__device__ float g_y  [(size_t)NSLOT * D_OUT];       // per-slot outputs

// ---------------- helpers ---------------------------------------------------
__device__ __forceinline__ uint32_t smem_u32(const void* p) {
    uint32_t a;
    asm("{ .reg .u64 t; cvta.to.shared.u64 t, %1; cvt.u32.u64 %0, t; }" : "=r"(a) : "l"(p));
    return a;
}
__device__ __forceinline__ void cpa16(uint32_t dst, const void* src) {
    asm volatile("cp.async.cg.shared.global [%0], [%1], 16;" :: "r"(dst), "l"(src));
}
#define CP_COMMIT() asm volatile("cp.async.commit_group;" ::: "memory")
#define CP_WAIT1()  asm volatile("cp.async.wait_group 1;" ::: "memory")
#define CP_WAIT2()  asm volatile("cp.async.wait_group 2;" ::: "memory")

__device__ __forceinline__ void mma_f16(float c[4], const uint32_t a[4], const uint32_t b[2]) {
    asm volatile(
        "mma.sync.aligned.m16n8k16.row.col.f32.f16.f16.f32 "
        "{%0,%1,%2,%3}, {%4,%5,%6,%7}, {%8,%9}, {%0,%1,%2,%3};"
        : "+f"(c[0]), "+f"(c[1]), "+f"(c[2]), "+f"(c[3])
        : "r"(a[0]), "r"(a[1]), "r"(a[2]), "r"(a[3]), "r"(b[0]), "r"(b[1]));
}
__device__ __forceinline__ void ldsm_x4(uint32_t r[4], uint32_t addr) {
    asm volatile("ldmatrix.sync.aligned.m8n8.x4.shared.b16 {%0,%1,%2,%3}, [%4];"
        : "=r"(r[0]), "=r"(r[1]), "=r"(r[2]), "=r"(r[3]) : "r"(addr));
}
__device__ __forceinline__ u16 to_h(float v) {
    return __half_as_ushort(__float2half(v));
}

// ---------------- reset / gating(+pack x) / scan / scatter -------------------
__global__ void reset_kernel() {
    int i = threadIdx.x;
    if (i < E_EXP) g_counts[i] = 0;
}

__global__ void gating_kernel(const float* __restrict__ x,
                              const float* __restrict__ Wg,
                              const float* __restrict__ bg) {
    int warp = (blockIdx.x * blockDim.x + threadIdx.x) >> 5;
    int lane = threadIdx.x & 31;
    if (warp >= BATCH) return;
    const float* xr = x + (size_t)warp * D_IN;

    float acc[E_EXP];
#pragma unroll
    for (int e = 0; e < E_EXP; e++) acc[e] = 0.f;
#pragma unroll
    for (int i = 0; i < D_IN / 32; i++) {
        float xv = xr[i * 32 + lane];
        g_xh[(size_t)warp * D_IN + i * 32 + lane] = to_h(xv);   // fused fp16 pack
        const float* wr = Wg + (size_t)(i * 32 + lane) * E_EXP;
#pragma unroll
        for (int e = 0; e < E_EXP; e++) acc[e] = fmaf(xv, wr[e], acc[e]);
    }
#pragma unroll
    for (int e = 0; e < E_EXP; e++) {
        float v = acc[e];
        v += __shfl_xor_sync(0xffffffffu, v, 16);
        v += __shfl_xor_sync(0xffffffffu, v, 8);
        v += __shfl_xor_sync(0xffffffffu, v, 4);
        v += __shfl_xor_sync(0xffffffffu, v, 2);
        v += __shfl_xor_sync(0xffffffffu, v, 1);
        acc[e] = v + bg[e];
    }
    if (lane == 0) {
        int i0 = 0; float v0 = acc[0];
#pragma unroll
        for (int e = 1; e < E_EXP; e++)
            if (acc[e] > v0) { v0 = acc[e]; i0 = e; }
        int i1 = -1; float v1 = -3.4e38f;
#pragma unroll
        for (int e = 0; e < E_EXP; e++)
            if (e != i0 && acc[e] > v1) { v1 = acc[e]; i1 = e; }
        float w0 = 1.f / (1.f + expf(v1 - v0));
        g_topk_e[warp * 2 + 0] = i0;
        g_topk_e[warp * 2 + 1] = i1;
        g_topk_w[warp * 2 + 0] = w0;
        g_topk_w[warp * 2 + 1] = 1.f - w0;
        atomicAdd(&g_counts[i0], 1);
        atomicAdd(&g_counts[i1], 1);
    }
}

__global__ void scan_kernel() {
    if (threadIdx.x == 0) {
        int s = 0;
        for (int e = 0; e < E_EXP; e++) {
            g_offsets[e] = s;
            g_cursor[e]  = s;
            s += g_counts[e];
        }
        g_offsets[E_EXP] = s;
    }
}

__global__ void scatter_kernel() {
    __shared__ int hist[E_EXP];
    __shared__ int base[E_EXP];
    int tid = threadIdx.x;
    if (tid < E_EXP) hist[tid] = 0;
    __syncthreads();
    int i = blockIdx.x * 256 + tid;
    int e = g_topk_e[i];
    int rank = atomicAdd(&hist[e], 1);
    __syncthreads();
    if (tid < E_EXP) base[tid] = atomicAdd(&g_cursor[tid], hist[tid]);
    __syncthreads();
    g_perm[base[e] + rank] = i;
}

// ---------------- prep: weight transpose + fp16 ------------------------------
__global__ void pack_transpose_kernel(const float* __restrict__ in,
                                      int which, int Kd, int Nd) {
    u16* oh = which ? g_w2h : g_w1h;
    __shared__ float t[32][33];
    int e  = blockIdx.z;
    int k0 = blockIdx.x * 32, n0 = blockIdx.y * 32;
    const float* ine = in + (size_t)e * Kd * Nd;
    u16* ohe = oh + (size_t)e * Kd * Nd;
    int tx = threadIdx.x, ty = threadIdx.y;
#pragma unroll
    for (int i = 0; i < 4; i++) {
        int k = k0 + ty + i * 8;
        t[ty + i * 8][tx] = ine[(size_t)k * Nd + n0 + tx];
    }
    __syncthreads();
#pragma unroll
    for (int i = 0; i < 4; i++) {
        int n = n0 + ty + i * 8;
        ohe[(size_t)n * Kd + k0 + tx] = to_h(t[tx][ty + i * 8]);
    }
}

// ---------------- GEMM1: H = relu(X @ W1 + b1), A-resident, 2 B-buffers ------
// (exact R13 configuration: proven occ-2 at 105472 B)
#define G1_A    0
#define G1_B    81920
#define G1_BIAS 102400               // 512 floats
#define G1_SROW (G1_BIAS + 2048)     // 104448
#define G1_SENT (G1_SROW + 512)      // 104960
#define G1_SIZE (G1_SENT + 512)      // 105472

__global__ void __launch_bounds__(256, 2)
gemm1_kernel(const float* __restrict__ b1) {
    int e = blockIdx.y, tile = blockIdx.x;
    int beg = g_offsets[e];
    int cnt = g_offsets[e + 1] - beg;
    int m0  = tile * TM;
    if (m0 >= cnt) return;

    extern __shared__ char sm[];
    uint32_t smb = smem_u32(sm);
    int tid  = threadIdx.x;
    int wid  = tid >> 5, lane = tid & 31;
    int warpM = wid >> 1, warpN = wid & 1;      // 4 (M) x 2 (N)
    int lr = lane >> 2, lc2 = (lane & 3) * 2;

    int*   srow = (int*)(sm + G1_SROW);
    int*   sent = (int*)(sm + G1_SENT);
    float* bias = (float*)(sm + G1_BIAS);

    if (tid < TM) {
        int g = beg + m0 + tid;
        if (m0 + tid < cnt) {
            int entry = g_perm[g];
            srow[tid] = entry >> 1;
            sent[tid] = entry;
        } else {
            srow[tid] = 0;
            sent[tid] = -1;
        }
    }
    bias[tid]       = b1[e * D_H + tid];
    bias[tid + 256] = b1[e * D_H + tid + 256];
    __syncthreads();

    const char* Xh = (const char*)g_xh;
    const char* Wh = (const char*)g_w1h + (size_t)e * D_H * D_IN * 2;

    int row  = tid >> 1, half = tid & 1;
    int xrow = srow[row];

    // ---- prologue: A resident (8 slabs, one commit group) ----
    {
        size_t sa = ((size_t)xrow * D_IN + half * 16) * 2;
        uint32_t da = smb + G1_A + row * RSTRIDE + half * 32;
#pragma unroll
        for (int kc = 0; kc < 8; kc++) {
            cpa16(da + kc * PLANE,      Xh + sa + kc * 64);
            cpa16(da + kc * PLANE + 16, Xh + sa + kc * 64 + 16);
        }
        CP_COMMIT();
    }

#define G1_BISSUE(ITER, BUF)                                                       \
    do {                                                                           \
        int nc_ = (ITER) >> 3, kc_ = (ITER) & 7;                                   \
        uint32_t d = smb + G1_B + (BUF) * PLANE + row * RSTRIDE + half * 32;       \
        size_t sb = ((size_t)(nc_ * 128 + row) * D_IN + kc_ * 32 + half * 16) * 2; \
        cpa16(d,      Wh + sb);                                                    \
        cpa16(d + 16, Wh + sb + 16);                                               \
        CP_COMMIT();                                                               \
    } while (0)

    G1_BISSUE(0, 0);
    G1_BISSUE(1, 1);

    uint32_t aoff = (uint32_t)(warpM * 32 + (lane & 15)) * RSTRIDE + ((lane >> 4) << 4);
    uint32_t boff = (uint32_t)(warpN * 64 + (lane & 7) + (((lane >> 4) & 1) << 3)) * RSTRIDE
                  + (((lane >> 3) & 1) << 4);

    float c[2][8][4];

    for (int it = 0; it < 32; it++) {
        int nc = it >> 3, kc = it & 7, buf = it & 1;
        CP_WAIT1();
        __syncthreads();
        if (kc == 0) {
#pragma unroll
            for (int mi = 0; mi < 2; mi++)
#pragma unroll
                for (int ni = 0; ni < 8; ni++)
#pragma unroll
                    for (int q = 0; q < 4; q++) c[mi][ni][q] = 0.f;
        }
        uint32_t aBase = smb + G1_A + kc * PLANE + aoff;
        uint32_t bBase = smb + G1_B + buf * PLANE + boff;
#pragma unroll
        for (int k16 = 0; k16 < 2; k16++) {
            uint32_t ah[2][4], bh[8][2];
#pragma unroll
            for (int mi = 0; mi < 2; mi++)
                ldsm_x4(ah[mi], aBase + mi * (16 * RSTRIDE) + k16 * 32);
#pragma unroll
            for (int p = 0; p < 4; p++) {
                uint32_t r4[4];
                ldsm_x4(r4, bBase + p * (16 * RSTRIDE) + k16 * 32);
                bh[2 * p][0] = r4[0]; bh[2 * p][1] = r4[1];
                bh[2 * p + 1][0] = r4[2]; bh[2 * p + 1][1] = r4[3];
            }
#pragma unroll
            for (int mi = 0; mi < 2; mi++)
#pragma unroll
                for (int ni = 0; ni < 8; ni++) mma_f16(c[mi][ni], ah[mi], bh[ni]);
        }
        if (kc == 7) {
#pragma unroll
            for (int mi = 0; mi < 2; mi++) {
                int r0 = warpM * 32 + mi * 16 + lr;
#pragma unroll
                for (int ni = 0; ni < 8; ni++) {
                    int n = nc * 128 + warpN * 64 + ni * 8 + lc2;
                    float b0 = bias[n], b1v = bias[n + 1];
#pragma unroll
                    for (int hh = 0; hh < 2; hh++) {
                        int rr = r0 + hh * 8;
                        if (sent[rr] >= 0) {
                            float v0 = c[mi][ni][hh * 2 + 0] + b0;
                            float v1 = c[mi][ni][hh * 2 + 1] + b1v;
                            v0 = v0 > 0.f ? v0 : 0.f;
                            v1 = v1 > 0.f ? v1 : 0.f;
                            size_t o = (size_t)(beg + m0 + rr) * D_H + n;
                            *(uint32_t*)&g_hh[o] =
                                (uint32_t)to_h(v0) | ((uint32_t)to_h(v1) << 16);
                        }
                    }
                }
            }
        }
        __syncthreads();                 // all warps done reading B buf
        if (it + 2 < 32) G1_BISSUE(it + 2, buf);   // overlaps next iter's compute
    }
#undef G1_BISSUE
}

// ---------------- GEMM2: y = w * (H @ W2 + b2), 4-stage stream, 32x64 --------
#define STAGE2  (2 * PLANE)          // A|B per stage = 20480
#define G2_BIAS (4 * STAGE2)         // 81920: 256 floats
#define G2_SENT (G2_BIAS + 1024)     // 82944
#define G2_SW   (G2_SENT + 512)      // 83456
#define G2_SIZE (G2_SW + 512)        // 83968

__global__ void __launch_bounds__(256, 2)
gemm2_kernel(const float* __restrict__ b2) {
    int e = blockIdx.y, tile = blockIdx.x;
    int beg = g_offsets[e];
    int cnt = g_offsets[e + 1] - beg;
    int m0  = tile * TM;
    if (m0 >= cnt) return;

    extern __shared__ char sm[];
    uint32_t smb = smem_u32(sm);
    int tid  = threadIdx.x;
    int wid  = tid >> 5, lane = tid & 31;
    int warpM = wid >> 1, warpN = wid & 1;
    int lr = lane >> 2, lc2 = (lane & 3) * 2;

    int*   sent = (int*)(sm + G2_SENT);
    float* swv  = (float*)(sm + G2_SW);
    float* bias = (float*)(sm + G2_BIAS);

    if (tid < TM) {
        int g = beg + m0 + tid;
        if (m0 + tid < cnt) {
            int entry = g_perm[g];
            sent[tid] = entry;
            swv[tid]  = g_topk_w[entry];
        } else {
            sent[tid] = -1;
            swv[tid]  = 0.f;
        }
    }
    if (tid < 256) bias[tid] = b2[e * D_OUT + tid];
    __syncthreads();

    const char* Hh  = (const char*)g_hh;
    const char* W2h = (const char*)g_w2h + (size_t)e * D_OUT * D_H * 2;

    int row  = tid >> 1, half = tid & 1;
    int arow = (m0 + row < cnt) ? (beg + m0 + row) : beg;

#define G2_ISSUE(ITER, BUF)                                                        \
    do {                                                                           \
        int nc_ = (ITER) >> 4, kc_ = (ITER) & 15;                                  \
        uint32_t d = smb + (BUF) * STAGE2 + row * RSTRIDE + half * 32;             \
        size_t sa = ((size_t)arow * D_H + kc_ * 32 + half * 16) * 2;               \
        size_t sb = ((size_t)(nc_ * 128 + row) * D_H + kc_ * 32 + half * 16) * 2;  \
        cpa16(d,              Hh + sa);                                            \
        cpa16(d + 16,         Hh + sa + 16);                                       \
        cpa16(d + PLANE,      W2h + sb);                                           \
        cpa16(d + PLANE + 16, W2h + sb + 16);                                      \
        CP_COMMIT();                                                               \
    } while (0)

    G2_ISSUE(0, 0);
    G2_ISSUE(1, 1);
    G2_ISSUE(2, 2);

    uint32_t aoff = (uint32_t)(warpM * 32 + (lane & 15)) * RSTRIDE + ((lane >> 4) << 4);
    uint32_t boff = (uint32_t)(warpN * 64 + (lane & 7) + (((lane >> 4) & 1) << 3)) * RSTRIDE
                  + (((lane >> 3) & 1) << 4);

    float c[2][8][4];
    int buf = 0;

    for (int it = 0; it < 32; it++) {
        int nc = it >> 4, kc = it & 15;
        CP_WAIT2();
        __syncthreads();
        if (it + 3 < 32) {
            int nb = buf + 3; if (nb >= 4) nb -= 4;
            G2_ISSUE(it + 3, nb);
        }
        if (kc == 0) {
#pragma unroll
            for (int mi = 0; mi < 2; mi++)
#pragma unroll
                for (int ni = 0; ni < 8; ni++)
#pragma unroll
                    for (int q = 0; q < 4; q++) c[mi][ni][q] = 0.f;
        }
        uint32_t base  = smb + buf * STAGE2;
        uint32_t aBase = base + aoff;
        uint32_t bBase = base + PLANE + boff;
#pragma unroll
        for (int k16 = 0; k16 < 2; k16++) {
            uint32_t ah[2][4], bh[8][2];
#pragma unroll
            for (int mi = 0; mi < 2; mi++)
                ldsm_x4(ah[mi], aBase + mi * (16 * RSTRIDE) + k16 * 32);
#pragma unroll
            for (int p = 0; p < 4; p++) {
                uint32_t r4[4];
                ldsm_x4(r4, bBase + p * (16 * RSTRIDE) + k16 * 32);
                bh[2 * p][0] = r4[0]; bh[2 * p][1] = r4[1];
                bh[2 * p + 1][0] = r4[2]; bh[2 * p + 1][1] = r4[3];
            }
#pragma unroll
            for (int mi = 0; mi < 2; mi++)
#pragma unroll
                for (int ni = 0; ni < 8; ni++) mma_f16(c[mi][ni], ah[mi], bh[ni]);
        }
        if (kc == 15) {
#pragma unroll
            for (int mi = 0; mi < 2; mi++) {
                int r0 = warpM * 32 + mi * 16 + lr;
#pragma unroll
                for (int ni = 0; ni < 8; ni++) {
                    int n = nc * 128 + warpN * 64 + ni * 8 + lc2;
                    float b0 = bias[n], b1v = bias[n + 1];
#pragma unroll
                    for (int hh = 0; hh < 2; hh++) {
                        int rr = r0 + hh * 8;
                        int entry = sent[rr];
                        if (entry >= 0) {
                            float w = swv[rr];
                            float2 o;
                            o.x = w * (c[mi][ni][hh * 2 + 0] + b0);
                            o.y = w * (c[mi][ni][hh * 2 + 1] + b1v);
                            *(float2*)&g_y[(size_t)entry * D_OUT + n] = o;
                        }
                    }
                }
            }
        }
        if (++buf == 4) buf = 0;
    }
#undef G2_ISSUE
}

// ---------------- combine ---------------------------------------------------
__global__ void combine_kernel(float* __restrict__ out) {
    int i = blockIdx.x * blockDim.x + threadIdx.x;
    int b = i >> 6, q = i & 63;
    const float4* y4 = (const float4*)g_y;
    float4 u = y4[(size_t)(b * 2 + 0) * (D_OUT / 4) + q];
    float4 v = y4[(size_t)(b * 2 + 1) * (D_OUT / 4) + q];
    float4 o;
    o.x = u.x + v.x; o.y = u.y + v.y; o.z = u.z + v.z; o.w = u.w + v.w;
    ((float4*)out)[i] = o;
}

// ---------------- launch -----------------------------------------------------
extern "C" void kernel_launch(void* const* d_in, const int* in_sizes, int n_in,
                              void* d_out, int out_size) {
    const float* x  = (const float*)d_in[0];
    const float* Wg = (const float*)d_in[1];
    const float* bg = (const float*)d_in[2];
    const float* W1 = (const float*)d_in[3];
    const float* b1 = (const float*)d_in[4];
    const float* W2 = (const float*)d_in[5];
    const float* b2 = (const float*)d_in[6];
    float* out = (float*)d_out;

    cudaFuncSetAttribute(gemm1_kernel, cudaFuncAttributeMaxDynamicSharedMemorySize, G1_SIZE);
    cudaFuncSetAttribute(gemm2_kernel, cudaFuncAttributeMaxDynamicSharedMemorySize, G2_SIZE);

    reset_kernel<<<1, 32>>>();
    gating_kernel<<<BATCH / 8, 256>>>(x, Wg, bg);
    scan_kernel<<<1, 32>>>();
    scatter_kernel<<<NSLOT / 256, 256>>>();
    pack_transpose_kernel<<<dim3(D_IN / 32, D_H / 32, E_EXP), dim3(32, 8)>>>(W1, 0, D_IN, D_H);
    pack_transpose_kernel<<<dim3(D_H / 32, D_OUT / 32, E_EXP), dim3(32, 8)>>>(W2, 1, D_H, D_OUT);
    gemm1_kernel<<<dim3(NSLOT / TM, E_EXP), 256, G1_SIZE>>>(b1);
    gemm2_kernel<<<dim3(NSLOT / TM, E_EXP), 256, G2_SIZE>>>(b2);
    combine_kernel<<<(BATCH * (D_OUT / 4)) / 256, 256>>>(out);
}

// round 16
// speedup vs baseline: 1.0168x; 1.0091x over previous
#include <cuda_runtime.h>
#include <cuda_fp16.h>
#include <math.h>
#include <stdint.h>

typedef unsigned short u16;

#define E_EXP   16
#define TOPK    2
#define D_IN    256
#define D_H     512
#define D_OUT   256
#define BATCH   32768
#define NSLOT   (BATCH * TOPK)
#define TM      128

#define RSTRIDE 80               // padded smem row stride (A planes)
#define PLANE   (128 * RSTRIDE)  // 10240 B
#define BSWZ    8192             // swizzled B buffer: 128 rows x 64 B

// ---------------- scratch (__device__ globals) ------------------------------
__device__ int   g_counts[E_EXP];
__device__ int   g_offsets[E_EXP + 1];
__device__ int   g_cursor[E_EXP];
__device__ int   g_topk_e[NSLOT];
__device__ float g_topk_w[NSLOT];
__device__ int   g_perm[NSLOT];
__device__ u16   g_xh [(size_t)BATCH * D_IN];        // x fp16
__device__ u16   g_w1h[(size_t)E_EXP * D_H * D_IN];  // W1^T [e][n][k] fp16
__device__ u16   g_w2h[(size_t)E_EXP * D_OUT * D_H]; // W2^T [e][o][h] fp16
__device__ u16   g_hh [(size_t)NSLOT * D_H];         // H fp16
__device__ float g_y  [(size_t)NSLOT * D_OUT];       // per-slot outputs

// ---------------- helpers ---------------------------------------------------
__device__ __forceinline__ uint32_t smem_u32(const void* p) {
    uint32_t a;
    asm("{ .reg .u64 t; cvta.to.shared.u64 t, %1; cvt.u32.u64 %0, t; }" : "=r"(a) : "l"(p));
    return a;
}
__device__ __forceinline__ void cpa16(uint32_t dst, const void* src) {
    asm volatile("cp.async.cg.shared.global [%0], [%1], 16;" :: "r"(dst), "l"(src));
}
#define CP_COMMIT() asm volatile("cp.async.commit_group;" ::: "memory")
#define CP_WAIT1()  asm volatile("cp.async.wait_group 1;" ::: "memory")
#define CP_WAIT2()  asm volatile("cp.async.wait_group 2;" ::: "memory")

__device__ __forceinline__ void mma_f16(float c[4], const uint32_t a[4], const uint32_t b[2]) {
    asm volatile(
        "mma.sync.aligned.m16n8k16.row.col.f32.f16.f16.f32 "
        "{%0,%1,%2,%3}, {%4,%5,%6,%7}, {%8,%9}, {%0,%1,%2,%3};"
        : "+f"(c[0]), "+f"(c[1]), "+f"(c[2]), "+f"(c[3])
        : "r"(a[0]), "r"(a[1]), "r"(a[2]), "r"(a[3]), "r"(b[0]), "r"(b[1]));
}
__device__ __forceinline__ void ldsm_x4(uint32_t r[4], uint32_t addr) {
    asm volatile("ldmatrix.sync.aligned.m8n8.x4.shared.b16 {%0,%1,%2,%3}, [%4];"
        : "=r"(r[0]), "=r"(r[1]), "=r"(r[2]), "=r"(r[3]) : "r"(addr));
}
__device__ __forceinline__ u16 to_h(float v) {
    return __half_as_ushort(__float2half(v));
}
// B-buffer swizzle: row r, 16B unit offset u (bytes, multiple of 16)
__device__ __forceinline__ uint32_t bswz(int r, uint32_t u) {
    return (uint32_t)r * 64 + (u ^ ((((uint32_t)r >> 1) & 3) << 4));
}

// ---------------- reset / gating(+pack x) / scan / scatter -------------------
__global__ void reset_kernel() {
    int i = threadIdx.x;
    if (i < E_EXP) g_counts[i] = 0;
}

__global__ void gating_kernel(const float* __restrict__ x,
                              const float* __restrict__ Wg,
                              const float* __restrict__ bg) {
    int warp = (blockIdx.x * blockDim.x + threadIdx.x) >> 5;
    int lane = threadIdx.x & 31;
    if (warp >= BATCH) return;
    const float* xr = x + (size_t)warp * D_IN;

    float acc[E_EXP];
#pragma unroll
    for (int e = 0; e < E_EXP; e++) acc[e] = 0.f;
#pragma unroll
    for (int i = 0; i < D_IN / 32; i++) {
        float xv = xr[i * 32 + lane];
        g_xh[(size_t)warp * D_IN + i * 32 + lane] = to_h(xv);   // fused fp16 pack
        const float* wr = Wg + (size_t)(i * 32 + lane) * E_EXP;
#pragma unroll
        for (int e = 0; e < E_EXP; e++) acc[e] = fmaf(xv, wr[e], acc[e]);
    }
#pragma unroll
    for (int e = 0; e < E_EXP; e++) {
        float v = acc[e];
        v += __shfl_xor_sync(0xffffffffu, v, 16);
        v += __shfl_xor_sync(0xffffffffu, v, 8);
        v += __shfl_xor_sync(0xffffffffu, v, 4);
        v += __shfl_xor_sync(0xffffffffu, v, 2);
        v += __shfl_xor_sync(0xffffffffu, v, 1);
        acc[e] = v + bg[e];
    }
    if (lane == 0) {
        int i0 = 0; float v0 = acc[0];
#pragma unroll
        for (int e = 1; e < E_EXP; e++)
            if (acc[e] > v0) { v0 = acc[e]; i0 = e; }
        int i1 = -1; float v1 = -3.4e38f;
#pragma unroll
        for (int e = 0; e < E_EXP; e++)
            if (e != i0 && acc[e] > v1) { v1 = acc[e]; i1 = e; }
        float w0 = 1.f / (1.f + expf(v1 - v0));
        g_topk_e[warp * 2 + 0] = i0;
        g_topk_e[warp * 2 + 1] = i1;
        g_topk_w[warp * 2 + 0] = w0;
        g_topk_w[warp * 2 + 1] = 1.f - w0;
        atomicAdd(&g_counts[i0], 1);
        atomicAdd(&g_counts[i1], 1);
    }
}

__global__ void scan_kernel() {
    if (threadIdx.x == 0) {
        int s = 0;
        for (int e = 0; e < E_EXP; e++) {
            g_offsets[e] = s;
            g_cursor[e]  = s;
            s += g_counts[e];
        }
        g_offsets[E_EXP] = s;
    }
}

__global__ void scatter_kernel() {
    __shared__ int hist[E_EXP];
    __shared__ int base[E_EXP];
    int tid = threadIdx.x;
    if (tid < E_EXP) hist[tid] = 0;
    __syncthreads();
    int i = blockIdx.x * 256 + tid;
    int e = g_topk_e[i];
    int rank = atomicAdd(&hist[e], 1);
    __syncthreads();
    if (tid < E_EXP) base[tid] = atomicAdd(&g_cursor[tid], hist[tid]);
    __syncthreads();
    g_perm[base[e] + rank] = i;
}

// ---------------- prep: weight transpose + fp16 ------------------------------
__global__ void pack_transpose_kernel(const float* __restrict__ in,
                                      int which, int Kd, int Nd) {
    u16* oh = which ? g_w2h : g_w1h;
    __shared__ float t[32][33];
    int e  = blockIdx.z;
    int k0 = blockIdx.x * 32, n0 = blockIdx.y * 32;
    const float* ine = in + (size_t)e * Kd * Nd;
    u16* ohe = oh + (size_t)e * Kd * Nd;
    int tx = threadIdx.x, ty = threadIdx.y;
#pragma unroll
    for (int i = 0; i < 4; i++) {
        int k = k0 + ty + i * 8;
        t[ty + i * 8][tx] = ine[(size_t)k * Nd + n0 + tx];
    }
    __syncthreads();
#pragma unroll
    for (int i = 0; i < 4; i++) {
        int n = n0 + ty + i * 8;
        ohe[(size_t)n * Kd + k0 + tx] = to_h(t[tx][ty + i * 8]);
    }
}

// ---------------- GEMM1: A-resident, 3 swizzled B-buffers, single-sync -------
// smem: A 8 slabs padded (81920) | B 3x8192 swizzled (24576) | bias/srow/sent
#define G1_A    0
#define G1_B    81920
#define G1_BIAS 106496               // 512 floats
#define G1_SROW (G1_BIAS + 2048)     // 108544
#define G1_SENT (G1_SROW + 512)      // 109056
#define G1_SIZE (G1_SENT + 512)      // 109568

__global__ void __launch_bounds__(256, 2)
gemm1_kernel(const float* __restrict__ b1) {
    int e = blockIdx.y, tile = blockIdx.x;
    int beg = g_offsets[e];
    int cnt = g_offsets[e + 1] - beg;
    int m0  = tile * TM;
    if (m0 >= cnt) return;

    extern __shared__ char sm[];
    uint32_t smb = smem_u32(sm);
    int tid  = threadIdx.x;
    int wid  = tid >> 5, lane = tid & 31;
    int warpM = wid >> 1, warpN = wid & 1;      // 4 (M) x 2 (N)
    int lr = lane >> 2, lc2 = (lane & 3) * 2;

    int*   srow = (int*)(sm + G1_SROW);
    int*   sent = (int*)(sm + G1_SENT);
    float* bias = (float*)(sm + G1_BIAS);

    if (tid < TM) {
        int g = beg + m0 + tid;
        if (m0 + tid < cnt) {
            int entry = g_perm[g];
            srow[tid] = entry >> 1;
            sent[tid] = entry;
        } else {
            srow[tid] = 0;
            sent[tid] = -1;
        }
    }
    bias[tid]       = b1[e * D_H + tid];
    bias[tid + 256] = b1[e * D_H + tid + 256];
    __syncthreads();

    const char* Xh = (const char*)g_xh;
    const char* Wh = (const char*)g_w1h + (size_t)e * D_H * D_IN * 2;

    int row  = tid >> 1, half = tid & 1;
    int xrow = srow[row];

    // ---- prologue: A resident (8 slabs, one commit group) ----
    {
        size_t sa = ((size_t)xrow * D_IN + half * 16) * 2;
        uint32_t da = smb + G1_A + row * RSTRIDE + half * 32;
#pragma unroll
        for (int kc = 0; kc < 8; kc++) {
            cpa16(da + kc * PLANE,      Xh + sa + kc * 64);
            cpa16(da + kc * PLANE + 16, Xh + sa + kc * 64 + 16);
        }
        CP_COMMIT();
    }

    // B loader: row = tid>>1 loads 16B units (half*2, half*2+1) with swizzle
#define G1_BISSUE(ITER, BUF)                                                       \
    do {                                                                           \
        int nc_ = (ITER) >> 3, kc_ = (ITER) & 7;                                   \
        uint32_t db = smb + G1_B + (BUF) * BSWZ;                                   \
        size_t sb = ((size_t)(nc_ * 128 + row) * D_IN + kc_ * 32 + half * 16) * 2; \
        cpa16(db + bswz(row, (uint32_t)half * 32),      Wh + sb);                  \
        cpa16(db + bswz(row, (uint32_t)half * 32 + 16), Wh + sb + 16);             \
        CP_COMMIT();                                                               \
    } while (0)

    G1_BISSUE(0, 0);
    G1_BISSUE(1, 1);

    uint32_t aoff = (uint32_t)(warpM * 32 + (lane & 15)) * RSTRIDE + ((lane >> 4) << 4);
    // B ldmatrix lane addressing (swizzled)
    int rB_base = warpN * 64 + (lane & 7) + (((lane >> 4) & 1) << 3);
    uint32_t csel = (((uint32_t)lane >> 3) & 1) << 4;
    uint32_t brow[4], bxor[4];
#pragma unroll
    for (int p = 0; p < 4; p++) {
        int rB = rB_base + p * 16;
        brow[p] = (uint32_t)rB * 64;
        bxor[p] = ((((uint32_t)rB >> 1) & 3) << 4);
    }

    float c[2][8][4];
    int buf = 0;

    for (int it = 0; it < 32; it++) {
        int nc = it >> 3, kc = it & 7;
        CP_WAIT1();
        __syncthreads();
        if (it + 2 < 32) {                        // buf (it+2)%3 was consumed at it-1
            int nb = buf + 2; if (nb >= 3) nb -= 3;
            G1_BISSUE(it + 2, nb);
        }
        if (kc == 0) {
#pragma unroll
            for (int mi = 0; mi < 2; mi++)
#pragma unroll
                for (int ni = 0; ni < 8; ni++)
#pragma unroll
                    for (int q = 0; q < 4; q++) c[mi][ni][q] = 0.f;
        }
        uint32_t aBase = smb + G1_A + kc * PLANE + aoff;
        uint32_t bBase = smb + G1_B + buf * BSWZ;
#pragma unroll
        for (int k16 = 0; k16 < 2; k16++) {
            uint32_t ah[2][4], bh[8][2];
#pragma unroll
            for (int mi = 0; mi < 2; mi++)
                ldsm_x4(ah[mi], aBase + mi * (16 * RSTRIDE) + k16 * 32);
#pragma unroll
            for (int p = 0; p < 4; p++) {
                uint32_t r4[4];
                ldsm_x4(r4, bBase + brow[p] + ((((uint32_t)k16 << 5) | csel) ^ bxor[p]));
                bh[2 * p][0] = r4[0]; bh[2 * p][1] = r4[1];
                bh[2 * p + 1][0] = r4[2]; bh[2 * p + 1][1] = r4[3];
            }
#pragma unroll
            for (int mi = 0; mi < 2; mi++)
#pragma unroll
                for (int ni = 0; ni < 8; ni++) mma_f16(c[mi][ni], ah[mi], bh[ni]);
        }
        if (kc == 7) {
#pragma unroll
            for (int mi = 0; mi < 2; mi++) {
                int r0 = warpM * 32 + mi * 16 + lr;
#pragma unroll
                for (int ni = 0; ni < 8; ni++) {
                    int n = nc * 128 + warpN * 64 + ni * 8 + lc2;
                    float b0 = bias[n], b1v = bias[n + 1];
#pragma unroll
                    for (int hh = 0; hh < 2; hh++) {
                        int rr = r0 + hh * 8;
                        if (sent[rr] >= 0) {
                            float v0 = c[mi][ni][hh * 2 + 0] + b0;
                            float v1 = c[mi][ni][hh * 2 + 1] + b1v;
                            v0 = v0 > 0.f ? v0 : 0.f;
                            v1 = v1 > 0.f ? v1 : 0.f;
                            size_t o = (size_t)(beg + m0 + rr) * D_H + n;
                            *(uint32_t*)&g_hh[o] =
                                (uint32_t)to_h(v0) | ((uint32_t)to_h(v1) << 16);
                        }
                    }
                }
            }
        }
        if (++buf == 3) buf = 0;
    }
#undef G1_BISSUE
}

// ---------------- GEMM2: y = w * (H @ W2 + b2), 4-stage stream, 32x64 --------
#define STAGE2  (2 * PLANE)          // A|B per stage = 20480
#define G2_BIAS (4 * STAGE2)         // 81920: 256 floats
#define G2_SENT (G2_BIAS + 1024)     // 82944
#define G2_SW   (G2_SENT + 512)      // 83456
#define G2_SIZE (G2_SW + 512)        // 83968

__global__ void __launch_bounds__(256, 2)
gemm2_kernel(const float* __restrict__ b2) {
    int e = blockIdx.y, tile = blockIdx.x;
    int beg = g_offsets[e];
    int cnt = g_offsets[e + 1] - beg;
    int m0  = tile * TM;
    if (m0 >= cnt) return;

    extern __shared__ char sm[];
    uint32_t smb = smem_u32(sm);
    int tid  = threadIdx.x;
    int wid  = tid >> 5, lane = tid & 31;
    int warpM = wid >> 1, warpN = wid & 1;
    int lr = lane >> 2, lc2 = (lane & 3) * 2;

    int*   sent = (int*)(sm + G2_SENT);
    float* swv  = (float*)(sm + G2_SW);
    float* bias = (float*)(sm + G2_BIAS);

    if (tid < TM) {
        int g = beg + m0 + tid;
        if (m0 + tid < cnt) {
            int entry = g_perm[g];
            sent[tid] = entry;
            swv[tid]  = g_topk_w[entry];
        } else {
            sent[tid] = -1;
            swv[tid]  = 0.f;
        }
    }
    if (tid < 256) bias[tid] = b2[e * D_OUT + tid];
    __syncthreads();

    const char* Hh  = (const char*)g_hh;
    const char* W2h = (const char*)g_w2h + (size_t)e * D_OUT * D_H * 2;

    int row  = tid >> 1, half = tid & 1;
    int arow = (m0 + row < cnt) ? (beg + m0 + row) : beg;

#define G2_ISSUE(ITER, BUF)                                                        \
    do {                                                                           \
        int nc_ = (ITER) >> 4, kc_ = (ITER) & 15;                                  \
        uint32_t d = smb + (BUF) * STAGE2 + row * RSTRIDE + half * 32;             \
        size_t sa = ((size_t)arow * D_H + kc_ * 32 + half * 16) * 2;               \
        size_t sb = ((size_t)(nc_ * 128 + row) * D_H + kc_ * 32 + half * 16) * 2;  \
        cpa16(d,              Hh + sa);                                            \
        cpa16(d + 16,         Hh + sa + 16);                                       \
        cpa16(d + PLANE,      W2h + sb);                                           \
        cpa16(d + PLANE + 16, W2h + sb + 16);                                      \
        CP_COMMIT();                                                               \
    } while (0)

    G2_ISSUE(0, 0);
    G2_ISSUE(1, 1);
    G2_ISSUE(2, 2);

    uint32_t aoff = (uint32_t)(warpM * 32 + (lane & 15)) * RSTRIDE + ((lane >> 4) << 4);
    uint32_t boff = (uint32_t)(warpN * 64 + (lane & 7) + (((lane >> 4) & 1) << 3)) * RSTRIDE
                  + (((lane >> 3) & 1) << 4);

    float c[2][8][4];
    int buf = 0;

    for (int it = 0; it < 32; it++) {
        int nc = it >> 4, kc = it & 15;
        CP_WAIT2();
        __syncthreads();
        if (it + 3 < 32) {
            int nb = buf + 3; if (nb >= 4) nb -= 4;
            G2_ISSUE(it + 3, nb);
        }
        if (kc == 0) {
#pragma unroll
            for (int mi = 0; mi < 2; mi++)
#pragma unroll
                for (int ni = 0; ni < 8; ni++)
#pragma unroll
                    for (int q = 0; q < 4; q++) c[mi][ni][q] = 0.f;
        }
        uint32_t base  = smb + buf * STAGE2;
        uint32_t aBase = base + aoff;
        uint32_t bBase = base + PLANE + boff;
#pragma unroll
        for (int k16 = 0; k16 < 2; k16++) {
            uint32_t ah[2][4], bh[8][2];
#pragma unroll
            for (int mi = 0; mi < 2; mi++)
                ldsm_x4(ah[mi], aBase + mi * (16 * RSTRIDE) + k16 * 32);
#pragma unroll
            for (int p = 0; p < 4; p++) {
                uint32_t r4[4];
                ldsm_x4(r4, bBase + p * (16 * RSTRIDE) + k16 * 32);
                bh[2 * p][0] = r4[0]; bh[2 * p][1] = r4[1];
                bh[2 * p + 1][0] = r4[2]; bh[2 * p + 1][1] = r4[3];
            }
#pragma unroll
            for (int mi = 0; mi < 2; mi++)
#pragma unroll
                for (int ni = 0; ni < 8; ni++) mma_f16(c[mi][ni], ah[mi], bh[ni]);
        }
        if (kc == 15) {
#pragma unroll
            for (int mi = 0; mi < 2; mi++) {
                int r0 = warpM * 32 + mi * 16 + lr;
#pragma unroll
                for (int ni = 0; ni < 8; ni++) {
                    int n = nc * 128 + warpN * 64 + ni * 8 + lc2;
                    float b0 = bias[n], b1v = bias[n + 1];
#pragma unroll
                    for (int hh = 0; hh < 2; hh++) {
                        int rr = r0 + hh * 8;
                        int entry = sent[rr];
                        if (entry >= 0) {
                            float w = swv[rr];
                            float2 o;
                            o.x = w * (c[mi][ni][hh * 2 + 0] + b0);
                            o.y = w * (c[mi][ni][hh * 2 + 1] + b1v);
                            *(float2*)&g_y[(size_t)entry * D_OUT + n] = o;
                        }
                    }
                }
            }
        }
        if (++buf == 4) buf = 0;
    }
#undef G2_ISSUE
}

// ---------------- combine ---------------------------------------------------
__global__ void combine_kernel(float* __restrict__ out) {
    int i = blockIdx.x * blockDim.x + threadIdx.x;
    int b = i >> 6, q = i & 63;
    const float4* y4 = (const float4*)g_y;
    float4 u = y4[(size_t)(b * 2 + 0) * (D_OUT / 4) + q];
    float4 v = y4[(size_t)(b * 2 + 1) * (D_OUT / 4) + q];
    float4 o;
    o.x = u.x + v.x; o.y = u.y + v.y; o.z = u.z + v.z; o.w = u.w + v.w;
    ((float4*)out)[i] = o;
}

// ---------------- launch -----------------------------------------------------
extern "C" void kernel_launch(void* const* d_in, const int* in_sizes, int n_in,
                              void* d_out, int out_size) {
    const float* x  = (const float*)d_in[0];
    const float* Wg = (const float*)d_in[1];
    const float* bg = (const float*)d_in[2];
    const float* W1 = (const float*)d_in[3];
    const float* b1 = (const float*)d_in[4];
    const float* W2 = (const float*)d_in[5];
    const float* b2 = (const float*)d_in[6];
    float* out = (float*)d_out;

    cudaFuncSetAttribute(gemm1_kernel, cudaFuncAttributeMaxDynamicSharedMemorySize, G1_SIZE);
    cudaFuncSetAttribute(gemm2_kernel, cudaFuncAttributeMaxDynamicSharedMemorySize, G2_SIZE);

    reset_kernel<<<1, 32>>>();
    gating_kernel<<<BATCH / 8, 256>>>(x, Wg, bg);
    scan_kernel<<<1, 32>>>();
    scatter_kernel<<<NSLOT / 256, 256>>>();
    pack_transpose_kernel<<<dim3(D_IN / 32, D_H / 32, E_EXP), dim3(32, 8)>>>(W1, 0, D_IN, D_H);
    pack_transpose_kernel<<<dim3(D_H / 32, D_OUT / 32, E_EXP), dim3(32, 8)>>>(W2, 1, D_H, D_OUT);
    gemm1_kernel<<<dim3(NSLOT / TM, E_EXP), 256, G1_SIZE>>>(b1);
    gemm2_kernel<<<dim3(NSLOT / TM, E_EXP), 256, G2_SIZE>>>(b2);
    combine_kernel<<<(BATCH * (D_OUT / 4)) / 256, 256>>>(out);
}

// round 17
// speedup vs baseline: 1.0378x; 1.0206x over previous
#include <cuda_runtime.h>
#include <cuda_fp16.h>
#include <math.h>
#include <stdint.h>

typedef unsigned short u16;

#define E_EXP   16
#define TOPK    2
#define D_IN    256
#define D_H     512
#define D_OUT   256
#define BATCH   32768
#define NSLOT   (BATCH * TOPK)
#define TM      128
#define NPERS   296              // persistent CTAs: 2 per SM x 148

#define RSTRIDE 80               // padded smem row stride (A planes)
#define PLANE   (128 * RSTRIDE)  // 10240 B
#define BSWZ    8192             // swizzled B buffer: 128 rows x 64 B

// ---------------- scratch (__device__ globals) ------------------------------
__device__ int   g_counts[E_EXP];
__device__ int   g_offsets[E_EXP + 1];
__device__ int   g_cursor[E_EXP];
__device__ int   g_topk_e[NSLOT];
__device__ float g_topk_w[NSLOT];
__device__ int   g_perm[NSLOT];
__device__ int   g_tile_e [1024];
__device__ int   g_tile_m0[1024];
__device__ int   g_ntiles;
__device__ int   g_wcnt1, g_wcnt2;
__device__ u16   g_xh [(size_t)BATCH * D_IN];        // x fp16
__device__ u16   g_w1h[(size_t)E_EXP * D_H * D_IN];  // W1^T [e][n][k] fp16
__device__ u16   g_w2h[(size_t)E_EXP * D_OUT * D_H]; // W2^T [e][o][h] fp16
__device__ u16   g_hh [(size_t)NSLOT * D_H];         // H fp16
__device__ float g_y  [(size_t)NSLOT * D_OUT];       // per-slot outputs

// ---------------- helpers ---------------------------------------------------
__device__ __forceinline__ uint32_t smem_u32(const void* p) {
    uint32_t a;
    asm("{ .reg .u64 t; cvta.to.shared.u64 t, %1; cvt.u32.u64 %0, t; }" : "=r"(a) : "l"(p));
    return a;
}
__device__ __forceinline__ void cpa16(uint32_t dst, const void* src) {
    asm volatile("cp.async.cg.shared.global [%0], [%1], 16;" :: "r"(dst), "l"(src));
}
#define CP_COMMIT() asm volatile("cp.async.commit_group;" ::: "memory")
#define CP_WAIT0()  asm volatile("cp.async.wait_group 0;" ::: "memory")
#define CP_WAIT1()  asm volatile("cp.async.wait_group 1;" ::: "memory")
#define CP_WAIT2()  asm volatile("cp.async.wait_group 2;" ::: "memory")

__device__ __forceinline__ void mma_f16(float c[4], const uint32_t a[4], const uint32_t b[2]) {
    asm volatile(
        "mma.sync.aligned.m16n8k16.row.col.f32.f16.f16.f32 "
        "{%0,%1,%2,%3}, {%4,%5,%6,%7}, {%8,%9}, {%0,%1,%2,%3};"
        : "+f"(c[0]), "+f"(c[1]), "+f"(c[2]), "+f"(c[3])
        : "r"(a[0]), "r"(a[1]), "r"(a[2]), "r"(a[3]), "r"(b[0]), "r"(b[1]));
}
__device__ __forceinline__ void ldsm_x4(uint32_t r[4], uint32_t addr) {
    asm volatile("ldmatrix.sync.aligned.m8n8.x4.shared.b16 {%0,%1,%2,%3}, [%4];"
        : "=r"(r[0]), "=r"(r[1]), "=r"(r[2]), "=r"(r[3]) : "r"(addr));
}
__device__ __forceinline__ u16 to_h(float v) {
    return __half_as_ushort(__float2half(v));
}
__device__ __forceinline__ uint32_t bswz(int r, uint32_t u) {
    return (uint32_t)r * 64 + (u ^ ((((uint32_t)r >> 1) & 3) << 4));
}

// ---------------- reset / gating(+pack x) / scan / scatter -------------------
__global__ void reset_kernel() {
    int i = threadIdx.x;
    if (i < E_EXP) g_counts[i] = 0;
    if (i == 0) { g_wcnt1 = 0; g_wcnt2 = 0; }
}

__global__ void gating_kernel(const float* __restrict__ x,
                              const float* __restrict__ Wg,
                              const float* __restrict__ bg) {
    int warp = (blockIdx.x * blockDim.x + threadIdx.x) >> 5;
    int lane = threadIdx.x & 31;
    if (warp >= BATCH) return;
    const float* xr = x + (size_t)warp * D_IN;

    float acc[E_EXP];
#pragma unroll
    for (int e = 0; e < E_EXP; e++) acc[e] = 0.f;
#pragma unroll
    for (int i = 0; i < D_IN / 32; i++) {
        float xv = xr[i * 32 + lane];
        g_xh[(size_t)warp * D_IN + i * 32 + lane] = to_h(xv);   // fused fp16 pack
        const float* wr = Wg + (size_t)(i * 32 + lane) * E_EXP;
#pragma unroll
        for (int e = 0; e < E_EXP; e++) acc[e] = fmaf(xv, wr[e], acc[e]);
    }
#pragma unroll
    for (int e = 0; e < E_EXP; e++) {
        float v = acc[e];
        v += __shfl_xor_sync(0xffffffffu, v, 16);
        v += __shfl_xor_sync(0xffffffffu, v, 8);
        v += __shfl_xor_sync(0xffffffffu, v, 4);
        v += __shfl_xor_sync(0xffffffffu, v, 2);
        v += __shfl_xor_sync(0xffffffffu, v, 1);
        acc[e] = v + bg[e];
    }
    if (lane == 0) {
        int i0 = 0; float v0 = acc[0];
#pragma unroll
        for (int e = 1; e < E_EXP; e++)
            if (acc[e] > v0) { v0 = acc[e]; i0 = e; }
        int i1 = -1; float v1 = -3.4e38f;
#pragma unroll
        for (int e = 0; e < E_EXP; e++)
            if (e != i0 && acc[e] > v1) { v1 = acc[e]; i1 = e; }
        float w0 = 1.f / (1.f + expf(v1 - v0));
        g_topk_e[warp * 2 + 0] = i0;
        g_topk_e[warp * 2 + 1] = i1;
        g_topk_w[warp * 2 + 0] = w0;
        g_topk_w[warp * 2 + 1] = 1.f - w0;
        atomicAdd(&g_counts[i0], 1);
        atomicAdd(&g_counts[i1], 1);
    }
}

__global__ void scan_kernel() {
    if (threadIdx.x == 0) {
        int s = 0;
        for (int e = 0; e < E_EXP; e++) {
            g_offsets[e] = s;
            g_cursor[e]  = s;
            s += g_counts[e];
        }
        g_offsets[E_EXP] = s;
        int nt = 0;
        for (int e = 0; e < E_EXP; e++) {
            int cnt = g_counts[e];
            for (int m0 = 0; m0 < cnt; m0 += TM) {
                g_tile_e[nt]  = e;
                g_tile_m0[nt] = m0;
                nt++;
            }
        }
        g_ntiles = nt;
    }
}

__global__ void scatter_kernel() {
    __shared__ int hist[E_EXP];
    __shared__ int base[E_EXP];
    int tid = threadIdx.x;
    if (tid < E_EXP) hist[tid] = 0;
    __syncthreads();
    int i = blockIdx.x * 256 + tid;
    int e = g_topk_e[i];
    int rank = atomicAdd(&hist[e], 1);
    __syncthreads();
    if (tid < E_EXP) base[tid] = atomicAdd(&g_cursor[tid], hist[tid]);
    __syncthreads();
    g_perm[base[e] + rank] = i;
}

// ---------------- prep: weight transpose + fp16 ------------------------------
__global__ void pack_transpose_kernel(const float* __restrict__ in,
                                      int which, int Kd, int Nd) {
    u16* oh = which ? g_w2h : g_w1h;
    __shared__ float t[32][33];
    int e  = blockIdx.z;
    int k0 = blockIdx.x * 32, n0 = blockIdx.y * 32;
    const float* ine = in + (size_t)e * Kd * Nd;
    u16* ohe = oh + (size_t)e * Kd * Nd;
    int tx = threadIdx.x, ty = threadIdx.y;
#pragma unroll
    for (int i = 0; i < 4; i++) {
        int k = k0 + ty + i * 8;
        t[ty + i * 8][tx] = ine[(size_t)k * Nd + n0 + tx];
    }
    __syncthreads();
#pragma unroll
    for (int i = 0; i < 4; i++) {
        int n = n0 + ty + i * 8;
        ohe[(size_t)n * Kd + k0 + tx] = to_h(t[tx][ty + i * 8]);
    }
}

// ---------------- GEMM1: persistent, A-resident, 3 swizzled B-buffers --------
#define G1_A    0
#define G1_B    81920
#define G1_BIAS 106496               // 512 floats
#define G1_SROW (G1_BIAS + 2048)     // 108544
#define G1_SENT (G1_SROW + 512)      // 109056
#define G1_WIDX (G1_SENT + 512)      // 109568
#define G1_SIZE (G1_WIDX + 16)       // 109584

__global__ void __launch_bounds__(256, 2)
gemm1_kernel(const float* __restrict__ b1) {
    extern __shared__ char sm[];
    uint32_t smb = smem_u32(sm);
    int tid  = threadIdx.x;
    int wid  = tid >> 5, lane = tid & 31;
    int warpM = wid >> 1, warpN = wid & 1;
    int lr = lane >> 2, lc2 = (lane & 3) * 2;

    int*   srow = (int*)(sm + G1_SROW);
    int*   sent = (int*)(sm + G1_SENT);
    float* bias = (float*)(sm + G1_BIAS);
    int*   widx = (int*)(sm + G1_WIDX);

    const char* Xh = (const char*)g_xh;
    int row  = tid >> 1, half = tid & 1;

    uint32_t aoff = (uint32_t)(warpM * 32 + (lane & 15)) * RSTRIDE + ((lane >> 4) << 4);
    int rB_base = warpN * 64 + (lane & 7) + (((lane >> 4) & 1) << 3);
    uint32_t csel = (((uint32_t)lane >> 3) & 1) << 4;
    uint32_t brow[4], bxor[4];
#pragma unroll
    for (int p = 0; p < 4; p++) {
        int rB = rB_base + p * 16;
        brow[p] = (uint32_t)rB * 64;
        bxor[p] = ((((uint32_t)rB >> 1) & 3) << 4);
    }

    for (;;) {
        if (tid == 0) *widx = atomicAdd(&g_wcnt1, 1);
        __syncthreads();
        int w = *widx;
        if (w >= g_ntiles) break;
        int e   = g_tile_e[w];
        int m0  = g_tile_m0[w];
        int beg = g_offsets[e];
        int cnt = g_offsets[e + 1] - beg;
        const char* Wh = (const char*)g_w1h + (size_t)e * D_H * D_IN * 2;

        if (tid < TM) {
            int g = beg + m0 + tid;
            if (m0 + tid < cnt) {
                int entry = g_perm[g];
                srow[tid] = entry >> 1;
                sent[tid] = entry;
            } else {
                srow[tid] = 0;
                sent[tid] = -1;
            }
        }
        bias[tid]       = b1[e * D_H + tid];
        bias[tid + 256] = b1[e * D_H + tid + 256];
        __syncthreads();

        int xrow = srow[row];
        // prologue: A resident (8 slabs, one commit group)
        {
            size_t sa = ((size_t)xrow * D_IN + half * 16) * 2;
            uint32_t da = smb + G1_A + row * RSTRIDE + half * 32;
#pragma unroll
            for (int kc = 0; kc < 8; kc++) {
                cpa16(da + kc * PLANE,      Xh + sa + kc * 64);
                cpa16(da + kc * PLANE + 16, Xh + sa + kc * 64 + 16);
            }
            CP_COMMIT();
        }

#define G1_BISSUE(ITER, BUF)                                                       \
    do {                                                                           \
        int nc_ = (ITER) >> 3, kc_ = (ITER) & 7;                                   \
        uint32_t db = smb + G1_B + (BUF) * BSWZ;                                   \
        size_t sb = ((size_t)(nc_ * 128 + row) * D_IN + kc_ * 32 + half * 16) * 2; \
        cpa16(db + bswz(row, (uint32_t)half * 32),      Wh + sb);                  \
        cpa16(db + bswz(row, (uint32_t)half * 32 + 16), Wh + sb + 16);             \
        CP_COMMIT();                                                               \
    } while (0)

        G1_BISSUE(0, 0);
        G1_BISSUE(1, 1);

        float c[2][8][4];
        int buf = 0;

        for (int it = 0; it < 32; it++) {
            int nc = it >> 3, kc = it & 7;
            if (it == 31) CP_WAIT0(); else CP_WAIT1();
            __syncthreads();
            if (it + 2 < 32) {
                int nb = buf + 2; if (nb >= 3) nb -= 3;
                G1_BISSUE(it + 2, nb);
            }
            if (kc == 0) {
#pragma unroll
                for (int mi = 0; mi < 2; mi++)
#pragma unroll
                    for (int ni = 0; ni < 8; ni++)
#pragma unroll
                        for (int q = 0; q < 4; q++) c[mi][ni][q] = 0.f;
            }
            uint32_t aBase = smb + G1_A + kc * PLANE + aoff;
            uint32_t bBase = smb + G1_B + buf * BSWZ;
#pragma unroll
            for (int k16 = 0; k16 < 2; k16++) {
                uint32_t ah[2][4], bh[8][2];
#pragma unroll
                for (int mi = 0; mi < 2; mi++)
                    ldsm_x4(ah[mi], aBase + mi * (16 * RSTRIDE) + k16 * 32);
#pragma unroll
                for (int p = 0; p < 4; p++) {
                    uint32_t r4[4];
                    ldsm_x4(r4, bBase + brow[p] + ((((uint32_t)k16 << 5) | csel) ^ bxor[p]));
                    bh[2 * p][0] = r4[0]; bh[2 * p][1] = r4[1];
                    bh[2 * p + 1][0] = r4[2]; bh[2 * p + 1][1] = r4[3];
                }
#pragma unroll
                for (int mi = 0; mi < 2; mi++)
#pragma unroll
                    for (int ni = 0; ni < 8; ni++) mma_f16(c[mi][ni], ah[mi], bh[ni]);
            }
            if (kc == 7) {
#pragma unroll
                for (int mi = 0; mi < 2; mi++) {
                    int r0 = warpM * 32 + mi * 16 + lr;
#pragma unroll
                    for (int ni = 0; ni < 8; ni++) {
                        int n = nc * 128 + warpN * 64 + ni * 8 + lc2;
                        float b0 = bias[n], b1v = bias[n + 1];
#pragma unroll
                        for (int hh = 0; hh < 2; hh++) {
                            int rr = r0 + hh * 8;
                            if (sent[rr] >= 0) {
                                float v0 = c[mi][ni][hh * 2 + 0] + b0;
                                float v1 = c[mi][ni][hh * 2 + 1] + b1v;
                                v0 = v0 > 0.f ? v0 : 0.f;
                                v1 = v1 > 0.f ? v1 : 0.f;
                                size_t o = (size_t)(beg + m0 + rr) * D_H + n;
                                *(uint32_t*)&g_hh[o] =
                                    (uint32_t)to_h(v0) | ((uint32_t)to_h(v1) << 16);
                            }
                        }
                    }
                }
            }
            if (++buf == 3) buf = 0;
        }
#undef G1_BISSUE
        __syncthreads();   // epilogue reads of sent/bias done before next tile
    }
}

// ---------------- GEMM2: persistent, 4-stage stream, 32x64 -------------------
#define STAGE2  (2 * PLANE)          // A|B per stage = 20480
#define G2_BIAS (4 * STAGE2)         // 81920: 256 floats
#define G2_SENT (G2_BIAS + 1024)     // 82944
#define G2_SW   (G2_SENT + 512)      // 83456
#define G2_WIDX (G2_SW + 512)        // 83968
#define G2_SIZE (G2_WIDX + 16)       // 83984

__global__ void __launch_bounds__(256, 2)
gemm2_kernel(const float* __restrict__ b2) {
    extern __shared__ char sm[];
    uint32_t smb = smem_u32(sm);
    int tid  = threadIdx.x;
    int wid  = tid >> 5, lane = tid & 31;
    int warpM = wid >> 1, warpN = wid & 1;
    int lr = lane >> 2, lc2 = (lane & 3) * 2;

    int*   sent = (int*)(sm + G2_SENT);
    float* swv  = (float*)(sm + G2_SW);
    float* bias = (float*)(sm + G2_BIAS);
    int*   widx = (int*)(sm + G2_WIDX);

    const char* Hh = (const char*)g_hh;
    int row  = tid >> 1, half = tid & 1;

    uint32_t aoff = (uint32_t)(warpM * 32 + (lane & 15)) * RSTRIDE + ((lane >> 4) << 4);
    uint32_t boff = (uint32_t)(warpN * 64 + (lane & 7) + (((lane >> 4) & 1) << 3)) * RSTRIDE
                  + (((lane >> 3) & 1) << 4);

    for (;;) {
        if (tid == 0) *widx = atomicAdd(&g_wcnt2, 1);
        __syncthreads();
        int w = *widx;
        if (w >= g_ntiles) break;
        int e   = g_tile_e[w];
        int m0  = g_tile_m0[w];
        int beg = g_offsets[e];
        int cnt = g_offsets[e + 1] - beg;
        const char* W2h = (const char*)g_w2h + (size_t)e * D_OUT * D_H * 2;

        if (tid < TM) {
            int g = beg + m0 + tid;
            if (m0 + tid < cnt) {
                int entry = g_perm[g];
                sent[tid] = entry;
                swv[tid]  = g_topk_w[entry];
            } else {
                sent[tid] = -1;
                swv[tid]  = 0.f;
            }
        }
        if (tid < 256) bias[tid] = b2[e * D_OUT + tid];
        __syncthreads();

        int arow = (m0 + row < cnt) ? (beg + m0 + row) : beg;

#define G2_ISSUE(ITER, BUF)                                                        \
    do {                                                                           \
        int nc_ = (ITER) >> 4, kc_ = (ITER) & 15;                                  \
        uint32_t d = smb + (BUF) * STAGE2 + row * RSTRIDE + half * 32;             \
        size_t sa = ((size_t)arow * D_H + kc_ * 32 + half * 16) * 2;               \
        size_t sb = ((size_t)(nc_ * 128 + row) * D_H + kc_ * 32 + half * 16) * 2;  \
        cpa16(d,              Hh + sa);                                            \
        cpa16(d + 16,         Hh + sa + 16);                                       \
        cpa16(d + PLANE,      W2h + sb);                                           \
        cpa16(d + PLANE + 16, W2h + sb + 16);                                      \
        CP_COMMIT();                                                               \
    } while (0)

        G2_ISSUE(0, 0);
        G2_ISSUE(1, 1);
        G2_ISSUE(2, 2);

        float c[2][8][4];
        int buf = 0;

        for (int it = 0; it < 32; it++) {
            int nc = it >> 4, kc = it & 15;
            if (it == 31) CP_WAIT0();
            else if (it == 30) CP_WAIT1();
            else CP_WAIT2();
            __syncthreads();
            if (it + 3 < 32) {
                int nb = buf + 3; if (nb >= 4) nb -= 4;
                G2_ISSUE(it + 3, nb);
            }
            if (kc == 0) {
#pragma unroll
                for (int mi = 0; mi < 2; mi++)
#pragma unroll
                    for (int ni = 0; ni < 8; ni++)
#pragma unroll
                        for (int q = 0; q < 4; q++) c[mi][ni][q] = 0.f;
            }
            uint32_t base  = smb + buf * STAGE2;
            uint32_t aBase = base + aoff;
            uint32_t bBase = base + PLANE + boff;
#pragma unroll
            for (int k16 = 0; k16 < 2; k16++) {
                uint32_t ah[2][4], bh[8][2];
#pragma unroll
                for (int mi = 0; mi < 2; mi++)
                    ldsm_x4(ah[mi], aBase + mi * (16 * RSTRIDE) + k16 * 32);
#pragma unroll
                for (int p = 0; p < 4; p++) {
                    uint32_t r4[4];
                    ldsm_x4(r4, bBase + p * (16 * RSTRIDE) + k16 * 32);
                    bh[2 * p][0] = r4[0]; bh[2 * p][1] = r4[1];
                    bh[2 * p + 1][0] = r4[2]; bh[2 * p + 1][1] = r4[3];
                }
#pragma unroll
                for (int mi = 0; mi < 2; mi++)
#pragma unroll
                    for (int ni = 0; ni < 8; ni++) mma_f16(c[mi][ni], ah[mi], bh[ni]);
            }
            if (kc == 15) {
#pragma unroll
                for (int mi = 0; mi < 2; mi++) {
                    int r0 = warpM * 32 + mi * 16 + lr;
#pragma unroll
                    for (int ni = 0; ni < 8; ni++) {
                        int n = nc * 128 + warpN * 64 + ni * 8 + lc2;
                        float b0 = bias[n], b1v = bias[n + 1];
#pragma unroll
                        for (int hh = 0; hh < 2; hh++) {
                            int rr = r0 + hh * 8;
                            int entry = sent[rr];
                            if (entry >= 0) {
                                float ww = swv[rr];
                                float2 o;
                                o.x = ww * (c[mi][ni][hh * 2 + 0] + b0);
                                o.y = ww * (c[mi][ni][hh * 2 + 1] + b1v);
                                *(float2*)&g_y[(size_t)entry * D_OUT + n] = o;
                            }
                        }
                    }
                }
            }
            if (++buf == 4) buf = 0;
        }
#undef G2_ISSUE
        __syncthreads();
    }
}

// ---------------- combine ---------------------------------------------------
__global__ void combine_kernel(float* __restrict__ out) {
    int i = blockIdx.x * blockDim.x + threadIdx.x;
    int b = i >> 6, q = i & 63;
    const float4* y4 = (const float4*)g_y;
    float4 u = y4[(size_t)(b * 2 + 0) * (D_OUT / 4) + q];
    float4 v = y4[(size_t)(b * 2 + 1) * (D_OUT / 4) + q];
    float4 o;
    o.x = u.x + v.x; o.y = u.y + v.y; o.z = u.z + v.z; o.w = u.w + v.w;
    ((float4*)out)[i] = o;
}

// ---------------- launch -----------------------------------------------------
extern "C" void kernel_launch(void* const* d_in, const int* in_sizes, int n_in,
                              void* d_out, int out_size) {
    const float* x  = (const float*)d_in[0];
    const float* Wg = (const float*)d_in[1];
    const float* bg = (const float*)d_in[2];
    const float* W1 = (const float*)d_in[3];
    const float* b1 = (const float*)d_in[4];
    const float* W2 = (const float*)d_in[5];
    const float* b2 = (const float*)d_in[6];
    float* out = (float*)d_out;

    cudaFuncSetAttribute(gemm1_kernel, cudaFuncAttributeMaxDynamicSharedMemorySize, G1_SIZE);
    cudaFuncSetAttribute(gemm2_kernel, cudaFuncAttributeMaxDynamicSharedMemorySize, G2_SIZE);

    reset_kernel<<<1, 32>>>();
    gating_kernel<<<BATCH / 8, 256>>>(x, Wg, bg);
    scan_kernel<<<1, 32>>>();
    scatter_kernel<<<NSLOT / 256, 256>>>();
    pack_transpose_kernel<<<dim3(D_IN / 32, D_H / 32, E_EXP), dim3(32, 8)>>>(W1, 0, D_IN, D_H);
    pack_transpose_kernel<<<dim3(D_H / 32, D_OUT / 32, E_EXP), dim3(32, 8)>>>(W2, 1, D_H, D_OUT);
    gemm1_kernel<<<NPERS, 256, G1_SIZE>>>(b1);
    gemm2_kernel<<<NPERS, 256, G2_SIZE>>>(b2);
    combine_kernel<<<(BATCH * (D_OUT / 4)) / 256, 256>>>(out);
}